// round 9
// baseline (speedup 1.0000x reference)
#include <cuda_runtime.h>

// B=1, C=32, H=128, W=256. ONE warp per right-feature row, lane l owns
// elements j = 8l..8l+7 (blocked). Global inclusive prefixes
// s[k] = base + ipfx[k] live in registers after one warp scan of lane
// totals. For the dataset's dmin=0, dmax=64 (distance 64 = 8 lanes):
//   hi = E[w+1]  = own s[k]
//   lo = E[w-63] = lane-8's s[k]  (one shfl_up by 8; lanes<8 -> 0)
// -> no shared memory, no __syncthreads, epilogue is pure register math.
// Generic (dmin,dmax) fallback uses a per-warp smem prefix table.

#define C_CH   32
#define H_DIM  128
#define W_DIM  256
#define FULLM  0xFFFFFFFFu
#define WPB    4              // warps (rows) per block
#define EPAD   260

__global__ __launch_bounds__(128) void gcnet_shfl_kernel(
        const float* __restrict__ feaR,
        const int* __restrict__ p_min,
        const int* __restrict__ p_max,
        float* __restrict__ out) {
    const int lane = threadIdx.x & 31;
    const int wrp  = threadIdx.x >> 5;                 // 0..3
    const int row  = blockIdx.x * WPB + wrp;           // 0..4095
    const int cr   = row >> 7;
    const int h    = row & 127;

    const int dmin = p_min[0] / 2;
    const int dmax = p_max[0] / 2;
    const int D    = dmax - dmin;
    const float mean_d  = 0.5f * (float)(dmin + dmax - 1);
    const float S_total = mean_d * (float)D;

    const int j0 = 8 * lane;

    // ---- load 8 contiguous elements (2 independent LDG.128, MLP=2) ----
    const float* rp = feaR + row * W_DIM + j0;
    const float4 a = *(const float4*)(rp);
    const float4 b = *(const float4*)(rp + 4);

    float p[8];
    p[0] = __expf(a.x); p[1] = __expf(a.y); p[2] = __expf(a.z); p[3] = __expf(a.w);
    p[4] = __expf(b.x); p[5] = __expf(b.y); p[6] = __expf(b.z); p[7] = __expf(b.w);

    // lane-local inclusive prefixes ipfx[k] = sum p[0..k], and Q analog
    const float jf = (float)j0;
    float ipf[8], iqf[8];
    float accp = 0.0f, accq = 0.0f;
    #pragma unroll
    for (int k = 0; k < 8; ++k) {
        accp += p[k];
        accq = fmaf(jf + (float)k, p[k], accq);
        ipf[k] = accp;
        iqf[k] = accq;
    }
    const float tp = accp, tq = accq;

    // ---- warp inclusive scan of lane totals ----
    float ip = tp, iq = tq;
    #pragma unroll
    for (int off = 1; off < 32; off <<= 1) {
        const float sp = __shfl_up_sync(FULLM, ip, off);
        const float sq = __shfl_up_sync(FULLM, iq, off);
        if (lane >= off) { ip += sp; iq += sq; }
    }
    const float basep = ip - tp;      // global exclusive offset for this lane
    const float baseq = iq - tq;

    // global inclusive prefixes at this lane's own positions: s[k] = E[w+1]
    float sp_[8], sq_[8];
    #pragma unroll
    for (int k = 0; k < 8; ++k) { sp_[k] = basep + ipf[k]; sq_[k] = baseq + iqf[k]; }

    // ---- left channel: constant fill (2 coalesced STG.128) ----
    {
        const float4 cst = make_float4(mean_d, mean_d, mean_d, mean_d);
        float* outL = out + (cr * H_DIM + h) * W_DIM + j0;
        *(float4*)(outL)     = cst;
        *(float4*)(outL + 4) = cst;
    }

    float res[8];
    float* outR = out + ((cr + C_CH) * H_DIM + h) * W_DIM;

    if (dmin == 0 && (dmax & 7) == 0 && dmax <= 256) {
        // ---- fast path: lo via shuffle by dmax/8 lanes ----
        const int ldist = dmax >> 3;                  // 8 for dmax=64
        const bool hasLo = (lane >= ldist);
        #pragma unroll
        for (int k = 0; k < 8; ++k) {
            const float lop = __shfl_up_sync(FULLM, sp_[k], ldist);
            const float loq = __shfl_up_sync(FULLM, sq_[k], ldist);
            const int   w   = j0 + k;
            const float wf  = (float)w;
            const float denv = sp_[k] - (hasLo ? lop : 0.0f);
            const float qd   = sq_[k] - (hasLo ? loq : 0.0f);
            // general per-output constants (collapse for full windows)
            const int   dhi = (dmax - 1) < w ? (dmax - 1) : w;
            const float nv  = (float)(dhi + 1);       // dmin = 0
            const float Sv  = 0.5f * (float)dhi * nv;
            const float num = fmaf(wf, denv, S_total - Sv) - qd;
            const float den = denv + ((float)D - nv);
            res[k] = __fdividef(num, den);
        }
        const float4 r0 = make_float4(res[0], res[1], res[2], res[3]);
        const float4 r1 = make_float4(res[4], res[5], res[6], res[7]);
        *(float4*)(outR + j0)     = r0;
        *(float4*)(outR + j0 + 4) = r1;
    } else {
        // ---- generic fallback: per-warp smem prefix table ----
        __shared__ float2 sE[WPB][EPAD];
        float2* E = sE[wrp];
        #pragma unroll
        for (int k = 0; k < 8; ++k)
            E[j0 + k + 1] = make_float2(sp_[k], sq_[k]);
        if (lane == 0) E[0] = make_float2(0.0f, 0.0f);
        __syncwarp();
        #pragma unroll
        for (int k = 0; k < 8; ++k) {
            const int w = j0 + k;
            int dlo = dmin > (w - W_DIM + 1) ? dmin : (w - W_DIM + 1);
            int dhi = (dmax - 1) < w ? (dmax - 1) : w;
            int nv  = dhi - dlo + 1;
            float denv = 0.0f, qd = 0.0f, Sv = 0.0f;
            if (nv > 0) {
                const float2 lo = E[w - dhi];
                const float2 hi = E[w - dlo + 1];
                denv = hi.x - lo.x;
                qd   = hi.y - lo.y;
                Sv   = 0.5f * (float)(dlo + dhi) * (float)nv;
            } else nv = 0;
            const float num = fmaf((float)w, denv, S_total - Sv) - qd;
            const float den = denv + (float)(D - nv);
            res[k] = __fdividef(num, den);
        }
        const float4 r0 = make_float4(res[0], res[1], res[2], res[3]);
        const float4 r1 = make_float4(res[4], res[5], res[6], res[7]);
        *(float4*)(outR + j0)     = r0;
        *(float4*)(outR + j0 + 4) = r1;
    }
}

extern "C" void kernel_launch(void* const* d_in, const int* in_sizes, int n_in,
                              void* d_out, int out_size) {
    // metadata order: feaL (unused), feaR, min_disp, max_disp
    const float* feaR = (const float*)d_in[1];
    const int* p_min  = (const int*)d_in[2];
    const int* p_max  = (const int*)d_in[3];
    float* out = (float*)d_out;

    const int rows = C_CH * H_DIM;                    // 4096 rows
    gcnet_shfl_kernel<<<rows / WPB, 32 * WPB>>>(feaR, p_min, p_max, out);
}